// round 7
// baseline (speedup 1.0000x reference)
#include <cuda_runtime.h>

// FlowNet2 Resample2d (kernel_size=1) bilinear warp — smem-staged gather.
//
// Measured model (R2-R6): scattered L1 gathers are sector-return-bandwidth
// bound (~3.65 wavefronts each, even on hits), and the 4 bilinear gathers
// re-read the same sector set 4x. Fix: stage each tile's input window into
// shared memory ONCE per channel (coalesced LDG + STS, 100% sector
// utilization), gather via LDS (conflict-cost ~1, not sector-cost ~3.65).
// Double-buffered; one barrier per channel; out-of-window lanes (unbounded
// N(0,1) flow tails) fall back to global loads for exact correctness.

#define BB 8
#define CC 32
#define HH 512
#define WW 512
#define HWSZ (HH * WW)   // 2^18

#define TW 32            // tile width (one warp per row)
#define TH 16            // tile height
#define WINW 48          // window cols: x in [x0-8, x0+39]
#define WINH 28          // window rows: y in [y0-6, y0+21]
#define WINSZ (WINW * WINH)  // 1344 floats

__device__ __forceinline__ int iclamp(int v, int lo, int hi) {
    return min(max(v, lo), hi);
}

__global__ __launch_bounds__(512, 3)
void resample2d_kernel(const float* __restrict__ in1,
                       const float* __restrict__ flow,
                       float* __restrict__ out) {
    __shared__ float buf[2][WINSZ];

    int blk = blockIdx.x;                 // 16 x-chunks * 32 y-chunks * 8 batches
    int x0 = (blk & 15) << 5;             // * TW
    int y0 = ((blk >> 4) & 31) << 4;      // * TH
    int b  = blk >> 9;

    int tid = threadIdx.x;
    int w = x0 + (tid & 31);
    int h = y0 + (tid >> 5);
    int hw = (h << 9) | w;

    const float* fl = flow + ((size_t)b << 19);
    float dx = __ldg(fl + hw);
    float dy = __ldg(fl + HWSZ + hw);

    float xf = (float)w + dx;
    float yf = (float)h + dy;
    float fx0 = floorf(xf);
    float fy0 = floorf(yf);
    float alpha = xf - fx0;
    float beta  = yf - fy0;

    int ix0 = (int)fx0;
    int iy0 = (int)fy0;
    int xL = iclamp(ix0,     0, WW - 1);
    int xR = iclamp(ix0 + 1, 0, WW - 1);
    int yT = iclamp(iy0,     0, HH - 1);
    int yB = iclamp(iy0 + 1, 0, HH - 1);

    float wTR = alpha * (1.0f - beta);
    float wBL = (1.0f - alpha) * beta;
    float wBR = alpha * beta;
    float wTL = 1.0f - wTR - wBL - wBR;

    // Window origin (may be off-image; staging clamps source coords).
    int wx0 = x0 - 8;
    int wy0 = y0 - 6;

    // Window-local corner coords.
    int lxL = xL - wx0, lxR = xR - wx0;
    int lyT = yT - wy0, lyB = yB - wy0;
    bool inwin = (lxL >= 0) & (lxR < WINW) & (lyT >= 0) & (lyB < WINH);

    int sTL = lyT * WINW + lxL;
    int sTR = lyT * WINW + lxR;
    int sBL = lyB * WINW + lxL;
    int sBR = lyB * WINW + lxR;

    const float* base = in1 + ((size_t)b << 23);
    // Global fallback offsets (for out-of-window lanes only).
    int gTL = (yT << 9) + xL, gTR = (yT << 9) + xR;
    int gBL = (yB << 9) + xL, gBR = (yB << 9) + xR;

    float* op = out + ((size_t)b << 23) + hw;

    // Precompute the 3 staging source offsets for this thread (same for all
    // channels up to the channel stride): window idx tid, tid+512, tid+1024.
    int soff[3];
    bool sval[3];
    #pragma unroll
    for (int i = 0; i < 3; i++) {
        int idx = tid + i * 512;
        sval[i] = (idx < WINSZ);
        int r = idx / WINW;
        int cc = idx - r * WINW;
        int gy = iclamp(wy0 + r, 0, HH - 1);
        int gx = iclamp(wx0 + cc, 0, WW - 1);
        soff[i] = (gy << 9) + gx;
    }

    // Stage channel 0 into buf[0].
    #pragma unroll
    for (int i = 0; i < 3; i++)
        if (sval[i]) buf[0][tid + i * 512] = __ldg(base + soff[i]);
    __syncthreads();

    for (int c = 0; c < CC; c++) {
        int off = c << 18;
        const float* bufc = buf[c & 1];

        // Prefetch next channel into the other buffer (LDG issued early,
        // STS lands before the barrier below).
        if (c + 1 < CC) {
            int noff = (c + 1) << 18;
            float s0 = sval[0] ? __ldg(base + noff + soff[0]) : 0.0f;
            float s1 = sval[1] ? __ldg(base + noff + soff[1]) : 0.0f;
            float s2 = sval[2] ? __ldg(base + noff + soff[2]) : 0.0f;
            float* nb = buf[(c + 1) & 1];
            if (sval[0]) nb[tid]        = s0;
            if (sval[1]) nb[tid + 512]  = s1;
            if (sval[2]) nb[tid + 1024] = s2;
        }

        float vTL, vTR, vBL, vBR;
        if (inwin) {
            vTL = bufc[sTL];
            vTR = bufc[sTR];
            vBL = bufc[sBL];
            vBR = bufc[sBR];
        } else {
            vTL = __ldg(base + off + gTL);
            vTR = __ldg(base + off + gTR);
            vBL = __ldg(base + off + gBL);
            vBR = __ldg(base + off + gBR);
        }

        op[off] = wTL * vTL + wTR * vTR + wBL * vBL + wBR * vBR;

        __syncthreads();   // buf[(c+1)&1] complete; buf[c&1] free for c+2
    }
}

extern "C" void kernel_launch(void* const* d_in, const int* in_sizes, int n_in,
                              void* d_out, int out_size) {
    const float* input1 = (const float*)d_in[0];
    const float* input2 = (const float*)d_in[1];
    float* out = (float*)d_out;

    const int blocks = 16 * 32 * BB;   // 4096 tiles of 32x16
    resample2d_kernel<<<blocks, 512>>>(input1, input2, out);
}

// round 8
// speedup vs baseline: 3.0834x; 3.0834x over previous
#include <cuda_runtime.h>

// FlowNet2 Resample2d (kernel_size=1) bilinear warp.
// input1: [B, C, H, W] float, input2 (flow): [B, 2, H, W] float
//
// Best structure (R6): scalar gathers, one thread per pixel, channel loop.
// Proven dead ends: vector loads on scattered gathers (pay per-4B slice),
// smem staging (LDS conflicts + instruction bloat), channel-lockstep barriers.
// R8 refinement: 32x8 tiles (deeper vertical stacking doubles cross-warp
// corner-row reuse in L1, shrinking per-block window to ~2.2KB/channel) and
// __stcg streaming stores (write-once output stops polluting L1/L2).

#define BB 8
#define CC 32
#define HH 512
#define WW 512
#define HWSZ (HH * WW)   // 2^18

__global__ __launch_bounds__(256, 8)
void resample2d_kernel(const float* __restrict__ in1,
                       const float* __restrict__ flow,
                       float* __restrict__ out) {
    // Block tile: 32 px wide x 8 rows. Grid = 16 x-chunks * 64 y-chunks * 8 b.
    int blk = blockIdx.x;
    int x0 = (blk & 15) << 5;           // x-chunk * 32
    int y0 = ((blk >> 4) & 63) << 3;    // y-chunk * 8
    int b  = blk >> 10;                 // batch

    int w = x0 + (threadIdx.x & 31);    // warp = one 32-px row
    int h = y0 + (threadIdx.x >> 5);
    int hw = (h << 9) | w;

    const float* fl = flow + ((size_t)b << 19); // b * 2 * HWSZ
    float dx = __ldg(fl + hw);
    float dy = __ldg(fl + HWSZ + hw);

    float xf = (float)w + dx;
    float yf = (float)h + dy;
    float x0f = floorf(xf);
    float y0f = floorf(yf);
    float alpha = xf - x0f;   // unclamped fractional weights
    float beta  = yf - y0f;

    int ix0 = (int)x0f;
    int iy0 = (int)y0f;
    int xL = min(max(ix0,     0), WW - 1);
    int xR = min(max(ix0 + 1, 0), WW - 1);
    int yT = min(max(iy0,     0), HH - 1);
    int yB = min(max(iy0 + 1, 0), HH - 1);

    float wTR = alpha * (1.0f - beta);
    float wBL = (1.0f - alpha) * beta;
    float wBR = alpha * beta;
    float wTL = 1.0f - wTR - wBL - wBR;

    const float* base = in1 + ((size_t)b << 23);   // b * C * HWSZ
    const float* pTL = base + ((yT << 9) + xL);
    const float* pTR = base + ((yT << 9) + xR);
    const float* pBL = base + ((yB << 9) + xL);
    const float* pBR = base + ((yB << 9) + xR);
    float* op = out + ((size_t)b << 23) + hw;

    #pragma unroll 4
    for (int c = 0; c < CC; c++) {
        int off = c << 18;   // c * HWSZ
        float v = wTL * __ldg(pTL + off)
                + wTR * __ldg(pTR + off)
                + wBL * __ldg(pBL + off)
                + wBR * __ldg(pBR + off);
        __stcg(op + off, v);   // streaming store: output never re-read
    }
}

extern "C" void kernel_launch(void* const* d_in, const int* in_sizes, int n_in,
                              void* d_out, int out_size) {
    const float* input1 = (const float*)d_in[0];
    const float* input2 = (const float*)d_in[1];
    float* out = (float*)d_out;

    const int blocks = 16 * 64 * BB;   // 8192 tiles of 32x8
    resample2d_kernel<<<blocks, 256>>>(input1, input2, out);
}